// round 1
// baseline (speedup 1.0000x reference)
#include <cuda_runtime.h>

// B3-spline undecimated (à trous) wavelet transform, J=3, fused single kernel.
// Input  x:   (8, 1024, 1024) fp32
// Output out: (8, 4, 1024, 1024) fp32 = [w1, w2, w3, c3]
//
// One block = one 64x64 output tile. Halo = 2*(1+2+4) = 14 per side -> 92x92
// input region loaded with reflect indexing (reflect composes through the
// symmetric kernel, so per-level reflect padding is reproduced exactly).
// Three smem buffers rotate through the separable H-conv/W-conv pipeline.
// Convs use dilation-phase register sliding windows: 1 LDS + 1 STS per elem.

namespace {

constexpr int TS    = 64;            // output tile side
constexpr int HALO  = 14;            // 2*1 + 2*2 + 2*4
constexpr int IN    = TS + 2 * HALO; // 92
constexpr int PITCH = IN + 1;        // 93 (odd -> bank-conflict-free both ways)
constexpr int NT    = 256;
constexpr int IMG_H = 1024, IMG_W = 1024;
constexpr int SMEM_ELEMS = IN * PITCH;
constexpr int SMEM_BYTES = 3 * SMEM_ELEMS * (int)sizeof(float);

constexpr float B3W0 = 0.0625f;  // 1/16
constexpr float B3W1 = 0.25f;    // 1/4
constexpr float B3W2 = 0.375f;   // 3/8

// Vertical 5-tap conv, dilation D, over rows [R0,R1) x cols [C0,C1).
// Unit = (column, row-segment). Each unit runs D phase streams, each a
// contiguous 5-register sliding window => 1 LDS per output.
template <int D, int R0, int R1, int C0, int C1, int NSEG>
__device__ __forceinline__ void hconv(const float* __restrict__ src,
                                      float* __restrict__ dst, int tid) {
    constexpr int NR = R1 - R0, NC = C1 - C0;
    constexpr int SEG = NR / NSEG;
    constexpr int NIT = SEG / D;
    constexpr int UNITS = NC * NSEG;
    static_assert(SEG * NSEG == NR, "rows divisible by NSEG");
    static_assert(NIT * D == SEG, "segment divisible by D");
    for (int u = tid; u < UNITS; u += NT) {
        const int c  = C0 + u % NC;
        const int rs = R0 + (u / NC) * SEG;
        const float* s = src + c;
        float* d = dst + c;
#pragma unroll
        for (int p = 0; p < D; ++p) {
            const int base = rs + p;
            float v0 = s[(base - 2 * D) * PITCH];
            float v1 = s[(base - D) * PITCH];
            float v2 = s[base * PITCH];
            float v3 = s[(base + D) * PITCH];
#pragma unroll
            for (int i = 0; i < NIT; ++i) {
                const int r = base + i * D;
                const float v4 = s[(r + 2 * D) * PITCH];
                d[r * PITCH] = B3W0 * (v0 + v4) + B3W1 * (v1 + v3) + B3W2 * v2;
                v0 = v1; v1 = v2; v2 = v3; v3 = v4;
            }
        }
    }
}

// Horizontal 5-tap conv, dilation D, over rows [R0,R1) x cols [C0,C1).
// Unit = (row, col-segment). Consecutive lanes get consecutive rows:
// addresses differ by PITCH=93 (coprime with 32) -> conflict-free.
template <int D, int R0, int R1, int C0, int C1, int NSEG>
__device__ __forceinline__ void wconv(const float* __restrict__ src,
                                      float* __restrict__ dst, int tid) {
    constexpr int NR = R1 - R0, NC = C1 - C0;
    constexpr int SEG = NC / NSEG;
    constexpr int NIT = SEG / D;
    constexpr int UNITS = NR * NSEG;
    static_assert(SEG * NSEG == NC, "cols divisible by NSEG");
    static_assert(NIT * D == SEG, "segment divisible by D");
    for (int u = tid; u < UNITS; u += NT) {
        const int r  = R0 + u % NR;
        const int cs = C0 + (u / NR) * SEG;
        const float* s = src + r * PITCH;
        float* d = dst + r * PITCH;
#pragma unroll
        for (int p = 0; p < D; ++p) {
            const int base = cs + p;
            float v0 = s[base - 2 * D];
            float v1 = s[base - D];
            float v2 = s[base];
            float v3 = s[base + D];
#pragma unroll
            for (int i = 0; i < NIT; ++i) {
                const int c = base + i * D;
                const float v4 = s[c + 2 * D];
                d[c] = B3W0 * (v0 + v4) + B3W1 * (v1 + v3) + B3W2 * v2;
                v0 = v1; v1 = v2; v2 = v3; v3 = v4;
            }
        }
    }
}

// Coalesced center write: out_ch = prev - cur over the 64x64 center, float4 STG.
__device__ __forceinline__ void diff_out(const float* __restrict__ prev,
                                         const float* __restrict__ cur,
                                         float* __restrict__ op, int tid) {
    for (int idx = tid; idx < TS * TS / 4; idx += NT) {
        const int r = idx >> 4;
        const int c = (idx & 15) << 2;
        const float* p = prev + (r + HALO) * PITCH + (c + HALO);
        const float* q = cur + (r + HALO) * PITCH + (c + HALO);
        const float4 v = make_float4(p[0] - q[0], p[1] - q[1],
                                     p[2] - q[2], p[3] - q[3]);
        *reinterpret_cast<float4*>(op + (size_t)r * IMG_W + c) = v;
    }
}

}  // namespace

__global__ void __launch_bounds__(NT, 2)
b3_uwt_kernel(const float* __restrict__ x, float* __restrict__ out) {
    extern __shared__ float sm[];
    float* Ab = sm;
    float* Tb = sm + SMEM_ELEMS;
    float* Bb = sm + 2 * SMEM_ELEMS;

    const int tid = threadIdx.x;
    const int gc0 = blockIdx.x * TS;
    const int gr0 = blockIdx.y * TS;
    const int b   = blockIdx.z;

    const float* xb = x + (size_t)b * IMG_H * IMG_W;

    // ---- load 92x92 input region with reflect indexing ----
    for (int idx = tid; idx < IN * IN; idx += NT) {
        const int r = idx / IN;
        const int c = idx - r * IN;
        int gr = gr0 + r - HALO;
        int gc = gc0 + c - HALO;
        gr = gr < 0 ? -gr : gr;
        gr = gr >= IMG_H ? 2 * IMG_H - 2 - gr : gr;
        gc = gc < 0 ? -gc : gc;
        gc = gc >= IMG_W ? 2 * IMG_W - 2 - gc : gc;
        Ab[r * PITCH + c] = __ldg(&xb[(size_t)gr * IMG_W + gc]);
    }
    __syncthreads();

    float* outb = out + ((size_t)b * 4) * IMG_H * IMG_W
                      + (size_t)gr0 * IMG_W + gc0;
    constexpr size_t CH = (size_t)IMG_H * IMG_W;

    // ---- level 0 (d=1): A -> T -> B ----
    hconv<1, 2, 90, 0, 92, 4>(Ab, Tb, tid);
    __syncthreads();
    wconv<1, 2, 90, 2, 90, 4>(Tb, Bb, tid);
    __syncthreads();

    // w1 = A - B (ch0); concurrently start level-1 H-conv (B -> T)
    diff_out(Ab, Bb, outb, tid);
    hconv<2, 6, 86, 2, 90, 4>(Bb, Tb, tid);
    __syncthreads();

    // ---- level 1 (d=2): T -> A (A is free after w1) ----
    wconv<2, 6, 86, 6, 86, 4>(Tb, Ab, tid);
    __syncthreads();

    // w2 = B - A (ch1); concurrently level-2 H-conv (A -> T)
    diff_out(Bb, Ab, outb + CH, tid);
    hconv<4, 14, 78, 6, 86, 4>(Ab, Tb, tid);
    __syncthreads();

    // ---- level 2 (d=4): T -> B (B is free after w2) ----
    wconv<4, 14, 78, 14, 78, 4>(Tb, Bb, tid);
    __syncthreads();

    // w3 = A - B (ch2), c3 = B (ch3)
    for (int idx = tid; idx < TS * TS / 4; idx += NT) {
        const int r = idx >> 4;
        const int c = (idx & 15) << 2;
        const float* p = Ab + (r + HALO) * PITCH + (c + HALO);
        const float* q = Bb + (r + HALO) * PITCH + (c + HALO);
        const float4 w3 = make_float4(p[0] - q[0], p[1] - q[1],
                                      p[2] - q[2], p[3] - q[3]);
        const float4 c3 = make_float4(q[0], q[1], q[2], q[3]);
        *reinterpret_cast<float4*>(outb + 2 * CH + (size_t)r * IMG_W + c) = w3;
        *reinterpret_cast<float4*>(outb + 3 * CH + (size_t)r * IMG_W + c) = c3;
    }
}

extern "C" void kernel_launch(void* const* d_in, const int* in_sizes, int n_in,
                              void* d_out, int out_size) {
    (void)in_sizes; (void)n_in; (void)out_size;
    const float* x = (const float*)d_in[0];
    float* out = (float*)d_out;

    cudaFuncSetAttribute(b3_uwt_kernel,
                         cudaFuncAttributeMaxDynamicSharedMemorySize,
                         SMEM_BYTES);

    dim3 grid(IMG_W / TS, IMG_H / TS, 8);  // 16 x 16 x 8
    b3_uwt_kernel<<<grid, NT, SMEM_BYTES>>>(x, out);
}

// round 2
// speedup vs baseline: 1.0698x; 1.0698x over previous
#include <cuda_runtime.h>

// B3-spline à-trous UWT, J=3, fused single kernel — float4-vectorized smem pipeline.
// Input  x:   (8, 1024, 1024) fp32 ; Output: (8, 4, 1024, 1024) fp32 = [w1,w2,w3,c3]
//
// One block = 64x64 output tile, halo 14 -> 92x92 region, reflect-indexed load
// (reflect composes through the symmetric kernel). 3 smem buffers, pitch 100
// floats with data at column offset 2 so all conv sub-ranges are 16B-aligned.
// All convs use float4 sliding register windows: 1 LDS.128 + 1 STS.128 per
// 4 outputs; pitch%32==4 banks -> conflict-free 128-bit row/col access.

namespace {

constexpr int TS    = 64;
constexpr int HALO  = 14;            // 2*(1+2+4)
constexpr int IN    = TS + 2 * HALO; // 92 rows
constexpr int PITCH = 100;           // floats; %32 == 4 -> conflict-free LDS.128
constexpr int COFF  = 2;             // data lives at abs cols [2, 94)
constexpr int NT    = 256;
constexpr int IMG_H = 1024, IMG_W = 1024;
constexpr int SMEM_ELEMS = IN * PITCH;          // 9200
constexpr int SMEM_BYTES = 3 * SMEM_ELEMS * 4;  // 110400

constexpr float B3W0 = 0.0625f;
constexpr float B3W1 = 0.25f;
constexpr float B3W2 = 0.375f;

__device__ __forceinline__ float4 ld4(const float* p) {
    return *reinterpret_cast<const float4*>(p);
}
__device__ __forceinline__ void st4(float* p, float4 v) {
    *reinterpret_cast<float4*>(p) = v;
}
__device__ __forceinline__ float b3s(float a, float b, float c, float d, float e) {
    return fmaf(c, B3W2, fmaf(b + d, B3W1, (a + e) * B3W0));
}
__device__ __forceinline__ float4 b3v(float4 a, float4 b, float4 c, float4 d, float4 e) {
    float4 r;
    r.x = b3s(a.x, b.x, c.x, d.x, e.x);
    r.y = b3s(a.y, b.y, c.y, d.y, e.y);
    r.z = b3s(a.z, b.z, c.z, d.z, e.z);
    r.w = b3s(a.w, b.w, c.w, d.w, e.w);
    return r;
}

// Vertical 5-tap conv, dilation D: rows [R0,R1) split into NSEGR segments,
// vec cols [VC0,VC1) (abs col = 4*vc). Unit = (vec col, row segment).
// Per unit: D phase streams, each a 5-deep float4 sliding window.
template <int D, int R0, int R1, int NSEGR, int VC0, int VC1>
__device__ __forceinline__ void hconv_v(const float* __restrict__ src,
                                        float* __restrict__ dst, int tid) {
    constexpr int NCV = VC1 - VC0;
    constexpr int NR  = R1 - R0;
    constexpr int SEG = NR / NSEGR;
    constexpr int NIT = SEG / D;
    constexpr int UNITS = NCV * NSEGR;
    static_assert(SEG * NSEGR == NR && NIT * D == SEG, "divisibility");
    for (int u = tid; u < UNITS; u += NT) {
        const int vc = VC0 + u % NCV;
        const int rs = R0 + (u / NCV) * SEG;
        const float* s = src + 4 * vc;
        float* d = dst + 4 * vc;
#pragma unroll
        for (int p = 0; p < D; ++p) {
            int r = rs + p;
            float4 v0 = ld4(s + (r - 2 * D) * PITCH);
            float4 v1 = ld4(s + (r - D) * PITCH);
            float4 v2 = ld4(s + r * PITCH);
            float4 v3 = ld4(s + (r + D) * PITCH);
#pragma unroll
            for (int i = 0; i < NIT; ++i, r += D) {
                const float4 v4 = ld4(s + (r + 2 * D) * PITCH);
                st4(d + r * PITCH, b3v(v0, v1, v2, v3, v4));
                v0 = v1; v1 = v2; v2 = v3; v3 = v4;
            }
        }
    }
}

// Horizontal 5-tap conv, dilation D: rows [R0,R1), output vec cols [VC0,VC1)
// split into NSEGC segments. Rolling register window of NV float4s; all tap
// indices compile-time. 4 outputs per LDS.128 after preload.
template <int D, int R0, int R1, int VC0, int VC1, int NSEGC>
__device__ __forceinline__ void wconv_v(const float* __restrict__ src,
                                        float* __restrict__ dst, int tid) {
    constexpr int NR   = R1 - R0;
    constexpr int NCV  = VC1 - VC0;
    constexpr int SEGV = NCV / NSEGC;
    constexpr int UNITS = NR * NSEGC;
    constexpr int BL = (D == 4) ? 2 : 1;  // vecs below base
    constexpr int TH = (D == 4) ? 2 : 1;  // vecs above base
    constexpr int NV = BL + 1 + TH;
    static_assert(SEGV * NSEGC == NCV, "divisibility");
    for (int u = tid; u < UNITS; u += NT) {
        const int r   = R0 + u % NR;
        const int vcs = VC0 + (u / NR) * SEGV;
        const float* s = src + r * PITCH;
        float* d = dst + r * PITCH;
        float w[4 * NV];
#pragma unroll
        for (int k = 0; k < NV; ++k) {
            const float4 t = ld4(s + 4 * (vcs - BL + k));
            w[4 * k + 0] = t.x; w[4 * k + 1] = t.y;
            w[4 * k + 2] = t.z; w[4 * k + 3] = t.w;
        }
#pragma unroll
        for (int i = 0; i < SEGV; ++i) {
            const int vc = vcs + i;
            constexpr int C = 4 * BL;
            float4 o;
            o.x = b3s(w[C - 2 * D],     w[C - D],     w[C],     w[C + D],     w[C + 2 * D]);
            o.y = b3s(w[C + 1 - 2 * D], w[C + 1 - D], w[C + 1], w[C + 1 + D], w[C + 1 + 2 * D]);
            o.z = b3s(w[C + 2 - 2 * D], w[C + 2 - D], w[C + 2], w[C + 2 + D], w[C + 2 + 2 * D]);
            o.w = b3s(w[C + 3 - 2 * D], w[C + 3 - D], w[C + 3], w[C + 3 + D], w[C + 3 + 2 * D]);
            st4(d + 4 * vc, o);
            if (i < SEGV - 1) {
#pragma unroll
                for (int k = 0; k < 4 * (NV - 1); ++k) w[k] = w[k + 4];
                const float4 t = ld4(s + 4 * (vc + 1 + TH));
                w[4 * NV - 4] = t.x; w[4 * NV - 3] = t.y;
                w[4 * NV - 2] = t.z; w[4 * NV - 1] = t.w;
            }
        }
    }
}

// Coalesced center diff write: out = prev - cur over 64x64, STG.128.
__device__ __forceinline__ void diff_out_v(const float* __restrict__ prev,
                                           const float* __restrict__ cur,
                                           float* __restrict__ op, int tid) {
    for (int idx = tid; idx < TS * TS / 4; idx += NT) {
        const int r  = idx >> 4;
        const int c4 = idx & 15;
        const int so = (HALO + r) * PITCH + (COFF + HALO) + 4 * c4;
        const float4 p = ld4(prev + so);
        const float4 q = ld4(cur + so);
        st4(op + (size_t)r * IMG_W + 4 * c4,
            make_float4(p.x - q.x, p.y - q.y, p.z - q.z, p.w - q.w));
    }
}

}  // namespace

__global__ void __launch_bounds__(NT, 2)
b3_uwt_kernel(const float* __restrict__ x, float* __restrict__ out) {
    extern __shared__ float sm[];
    float* Ab = sm;
    float* Tb = sm + SMEM_ELEMS;
    float* Bb = sm + 2 * SMEM_ELEMS;

    const int tid = threadIdx.x;
    const int gc0 = blockIdx.x * TS;
    const int gr0 = blockIdx.y * TS;
    const int b   = blockIdx.z;

    const float* xb = x + (size_t)b * IMG_H * IMG_W;

    // ---- load 92x92 region into A (abs cols [2,94)) ----
    const bool interior = (gr0 >= HALO) && (gr0 + TS + HALO <= IMG_H) &&
                          (gc0 >= HALO) && (gc0 + TS + HALO <= IMG_W);
    if (interior) {
        constexpr int L2N = IN / 2;  // 46 float2 per row
        const float* base = xb + (size_t)(gr0 - HALO) * IMG_W + (gc0 - HALO);
        for (int u = tid; u < IN * L2N; u += NT) {
            const int r = u / L2N;
            const int k = u - r * L2N;
            const float2 v =
                *reinterpret_cast<const float2*>(base + (size_t)r * IMG_W + 2 * k);
            *reinterpret_cast<float2*>(Ab + r * PITCH + COFF + 2 * k) = v;
        }
    } else {
        for (int idx = tid; idx < IN * IN; idx += NT) {
            const int r = idx / IN;
            const int c = idx - r * IN;
            int gr = gr0 + r - HALO;
            int gc = gc0 + c - HALO;
            gr = gr < 0 ? -gr : gr;
            gr = gr >= IMG_H ? 2 * IMG_H - 2 - gr : gr;
            gc = gc < 0 ? -gc : gc;
            gc = gc >= IMG_W ? 2 * IMG_W - 2 - gc : gc;
            Ab[r * PITCH + COFF + c] = __ldg(&xb[(size_t)gr * IMG_W + gc]);
        }
    }
    __syncthreads();

    float* outb = out + ((size_t)b * 4) * IMG_H * IMG_W
                      + (size_t)gr0 * IMG_W + gc0;
    constexpr size_t CHS = (size_t)IMG_H * IMG_W;

    // ---- level 0 (d=1): A -> T -> B ----
    hconv_v<1, 2, 90, 8, 0, 24>(Ab, Tb, tid);      // 192 units, seg 11 rows
    __syncthreads();
    wconv_v<1, 2, 90, 1, 23, 2>(Tb, Bb, tid);      // 176 units, seg 11 vecs
    __syncthreads();

    // w1 = A - B (ch0); level-1 H-conv (B -> T)
    diff_out_v(Ab, Bb, outb, tid);
    hconv_v<2, 6, 86, 10, 1, 23>(Bb, Tb, tid);     // 220 units, seg 8 rows
    __syncthreads();

    // ---- level 1 (d=2): T -> A ----
    wconv_v<2, 6, 86, 2, 22, 5>(Tb, Ab, tid);      // 400 units, seg 4 vecs
    __syncthreads();

    // w2 = B - A (ch1); level-2 H-conv (A -> T)
    diff_out_v(Bb, Ab, outb + CHS, tid);
    hconv_v<4, 14, 78, 8, 2, 22>(Ab, Tb, tid);     // 160 units, seg 8 rows
    __syncthreads();

    // ---- level 2 (d=4): T -> B ----
    wconv_v<4, 14, 78, 4, 20, 4>(Tb, Bb, tid);     // 256 units, seg 4 vecs
    __syncthreads();

    // w3 = A - B (ch2), c3 = B (ch3)
    for (int idx = tid; idx < TS * TS / 4; idx += NT) {
        const int r  = idx >> 4;
        const int c4 = idx & 15;
        const int so = (HALO + r) * PITCH + (COFF + HALO) + 4 * c4;
        const float4 p = ld4(Ab + so);
        const float4 q = ld4(Bb + so);
        st4(outb + 2 * CHS + (size_t)r * IMG_W + 4 * c4,
            make_float4(p.x - q.x, p.y - q.y, p.z - q.z, p.w - q.w));
        st4(outb + 3 * CHS + (size_t)r * IMG_W + 4 * c4, q);
    }
}

extern "C" void kernel_launch(void* const* d_in, const int* in_sizes, int n_in,
                              void* d_out, int out_size) {
    (void)in_sizes; (void)n_in; (void)out_size;
    const float* x = (const float*)d_in[0];
    float* out = (float*)d_out;

    cudaFuncSetAttribute(b3_uwt_kernel,
                         cudaFuncAttributeMaxDynamicSharedMemorySize,
                         SMEM_BYTES);

    dim3 grid(IMG_W / TS, IMG_H / TS, 8);  // 16 x 16 x 8
    b3_uwt_kernel<<<grid, NT, SMEM_BYTES>>>(x, out);
}